// round 3
// baseline (speedup 1.0000x reference)
#include <cuda_runtime.h>
#include <cuda_bf16.h>

#define T_LEN 4000
#define CHUNK 2000
#define NCHUNK 2
#define BLOCK 128
#define SEG 16          // outputs per thread per chunk (125 active threads)
#define HALO 32         // staged lookback (>= W), keeps banks conflict-free
#define W 24            // truncated EMA taps: (1-s)^24 ~ 8e-6
#define P(i) ((i) + ((i) >> 5))

__device__ __forceinline__ float fast_exp2(float x) {
    float y; asm("ex2.approx.ftz.f32 %0, %1;" : "=f"(y) : "f"(x)); return y;
}
__device__ __forceinline__ float fast_log2(float x) {
    float y; asm("lg2.approx.ftz.f32 %0, %1;" : "=f"(y) : "f"(x)); return y;
}
__device__ __forceinline__ float fast_sqrt(float x) {
    float y; asm("sqrt.approx.ftz.f32 %0, %1;" : "=f"(y) : "f"(x)); return y;
}

__global__ __launch_bounds__(BLOCK, 16) void pcen_kernel(
    const float* __restrict__ x,
    const float* __restrict__ alpha_p,
    const float* __restrict__ delta_p,
    const float* __restrict__ r_p,
    float* __restrict__ out)
{
    __shared__ float sh[P(HALO + CHUNK - 1) + 1];   // 2095 floats = 8380 B

    const int row = blockIdx.x;
    const int tid = threadIdx.x;
    const float* __restrict__ xr = x + (size_t)row * T_LEN;
    float* __restrict__ outr = out + (size_t)row * T_LEN;

    // scalar params (L1-broadcast)
    float alpha = fminf(fmaxf(alpha_p[0], 0.01f), 0.99f);
    float delta = fabsf(delta_p[0]) + 1e-6f;
    float r     = fminf(fmaxf(r_p[0], 0.01f), 1.0f);
    const bool  rhalf  = (r == 0.5f);
    const float dr     = rhalf ? fast_sqrt(delta)
                               : fast_exp2(r * fast_log2(delta));
    const float nalpha = -alpha;

    const float S    = 512.0f / 1323.0f;   // HOP/(SR*INIT_T) exact
    const float OMS  = 1.0f - S;
    const float INVS = 1323.0f / 512.0f;

    const bool active = (tid * SEG) < CHUNK;   // tid < 125
    const int  t0l    = HALO + tid * SEG;      // local index of first output

    #pragma unroll 1
    for (int c = 0; c < NCHUNK; c++) {
        const int gbase = c * CHUNK;

        // ---- stage chunk (+halo for c>0) into padded shared, float4 ----
        if (c == 0) {
            const float4* __restrict__ x4 = (const float4*)xr;
            #pragma unroll
            for (int i = tid; i < CHUNK / 4; i += BLOCK) {
                float4 v = x4[i];
                int b = HALO + 4 * i;
                sh[P(b + 0)] = v.x; sh[P(b + 1)] = v.y;
                sh[P(b + 2)] = v.z; sh[P(b + 3)] = v.w;
            }
        } else {
            const float4* __restrict__ x4 = (const float4*)(xr + gbase - HALO);
            #pragma unroll
            for (int i = tid; i < (CHUNK + HALO) / 4; i += BLOCK) {
                float4 v = x4[i];
                int b = 4 * i;
                sh[P(b + 0)] = v.x; sh[P(b + 1)] = v.y;
                sh[P(b + 2)] = v.z; sh[P(b + 3)] = v.w;
            }
        }
        __syncthreads();

        // ---- startup: reconstruct M at segment start ----
        float M = 0.0f;
        if (active) {
            const int t0g = gbase + tid * SEG;
            if (t0g < W) {
                // exact: M[t0] = sum_{j<t0} s(1-s)^j x[t0-j] + (1-s)^t0 x[0]
                float acc = 0.0f, wj = S;
                for (int j = 0; j < t0g; j++) {
                    acc += wj * sh[P(t0l - j)];
                    wj *= OMS;
                }
                acc += (wj * INVS) * sh[P(HALO)];
                M = acc;
            } else {
                float acc = 0.0f, wj = S;
                #pragma unroll
                for (int j = 0; j < W; j++) {
                    acc += wj * sh[P(t0l - j)];
                    wj *= OMS;
                }
                M = acc;
            }
        }
        // cross-thread window reads must finish before in-place overwrite
        __syncthreads();

        // ---- main loop: exact recurrence within segment; outputs in-place ----
        if (active) {
            if (rhalf) {
                #pragma unroll
                for (int j = 0; j < SEG; j++) {
                    float xv = sh[P(t0l + j)];
                    if (j > 0) M = OMS * M + S * xv;
                    float L    = fast_log2(1e-6f + M);
                    float sinv = fast_exp2(nalpha * L);
                    float bse  = fmaf(xv, sinv, delta);
                    sh[P(t0l + j)] = fast_sqrt(bse) - dr;
                }
            } else {
                #pragma unroll
                for (int j = 0; j < SEG; j++) {
                    float xv = sh[P(t0l + j)];
                    if (j > 0) M = OMS * M + S * xv;
                    float L    = fast_log2(1e-6f + M);
                    float sinv = fast_exp2(nalpha * L);
                    float bse  = fmaf(xv, sinv, delta);
                    sh[P(t0l + j)] = fast_exp2(r * fast_log2(bse)) - dr;
                }
            }
        }
        __syncthreads();

        // ---- coalesced writeback (float4) ----
        float4* __restrict__ o4 = (float4*)(outr + gbase);
        #pragma unroll
        for (int i = tid; i < CHUNK / 4; i += BLOCK) {
            int b = HALO + 4 * i;
            float4 v;
            v.x = sh[P(b + 0)]; v.y = sh[P(b + 1)];
            v.z = sh[P(b + 2)]; v.w = sh[P(b + 3)];
            o4[i] = v;
        }
        __syncthreads();   // buffer reused by next chunk's staging
    }
}

extern "C" void kernel_launch(void* const* d_in, const int* in_sizes, int n_in,
                              void* d_out, int out_size) {
    const float* mel   = (const float*)d_in[0];
    const float* alpha = (const float*)d_in[1];
    const float* delta = (const float*)d_in[2];
    const float* r     = (const float*)d_in[3];
    float* out = (float*)d_out;

    int rows = out_size / T_LEN;   // 128*128 = 16384
    pcen_kernel<<<rows, BLOCK>>>(mel, alpha, delta, r, out);
}

// round 4
// speedup vs baseline: 1.2924x; 1.2924x over previous
#include <cuda_runtime.h>
#include <cuda_bf16.h>

#define T_LEN 4000
#define BLOCK 128
#define SEG 32          // outputs per thread (125 active threads per row)
#define W 24            // truncated EMA lookback taps: (1-s)^24 ~ 8e-6
#define SH_PAD(i) ((i) + ((i) >> 5))

__device__ __forceinline__ float fast_exp2(float x) {
    float y; asm("ex2.approx.ftz.f32 %0, %1;" : "=f"(y) : "f"(x)); return y;
}
__device__ __forceinline__ float fast_log2(float x) {
    float y; asm("lg2.approx.ftz.f32 %0, %1;" : "=f"(y) : "f"(x)); return y;
}
__device__ __forceinline__ float fast_sqrt(float x) {
    float y; asm("sqrt.approx.ftz.f32 %0, %1;" : "=f"(y) : "f"(x)); return y;
}

__global__ __launch_bounds__(BLOCK) void pcen_kernel(
    const float* __restrict__ x,
    const float* __restrict__ alpha_p,
    const float* __restrict__ delta_p,
    const float* __restrict__ r_p,
    float* __restrict__ out)
{
    __shared__ float sh[T_LEN + (T_LEN >> 5)];  // 4125 floats, padded layout

    const int row = blockIdx.x;
    const int tid = threadIdx.x;
    const float* __restrict__ xr = x + (size_t)row * T_LEN;
    float* __restrict__ outr = out + (size_t)row * T_LEN;

    // ---- stage the row into padded shared (coalesced float4 global loads) ----
    const float4* __restrict__ x4 = (const float4*)xr;
    #pragma unroll
    for (int i = tid; i < T_LEN / 4; i += BLOCK) {
        float4 v = x4[i];
        int b = i * 4;
        sh[SH_PAD(b + 0)] = v.x;
        sh[SH_PAD(b + 1)] = v.y;
        sh[SH_PAD(b + 2)] = v.z;
        sh[SH_PAD(b + 3)] = v.w;
    }

    // ---- scalar params (L1-broadcast loads) ----
    float alpha = fminf(fmaxf(alpha_p[0], 0.01f), 0.99f);
    float delta = fabsf(delta_p[0]) + 1e-6f;
    float r     = fminf(fmaxf(r_p[0], 0.01f), 1.0f);
    const bool  rhalf  = (r == 0.5f);
    const float dr     = rhalf ? fast_sqrt(delta)
                               : fast_exp2(r * fast_log2(delta));
    const float nalpha = -alpha;

    __syncthreads();

    const float S   = 512.0f / 1323.0f;   // HOP/(SR*INIT_T), exact
    const float OMS = 1.0f - S;

    const int t0 = tid * SEG;
    float M = 0.0f;

    // ---- startup: reconstruct M at segment start via truncated window ----
    if (t0 < T_LEN) {
        if (t0 == 0) {
            M = sh[0];                    // exact init: M[0] = x[0]
        } else {
            // M(t0) ~= sum_{j=0}^{23} s*(1-s)^j * x[t0-j]
            float acc = 0.0f;
            float wj = S;
            #pragma unroll
            for (int j = 0; j < W; j++) {
                int t = t0 - j;
                acc += wj * sh[t + (t >> 5)];
                wj *= OMS;
            }
            M = acc;
        }
    }

    // All cross-thread window reads done before in-place overwrite below.
    __syncthreads();

    // ---- main loop: exact recurrence within segment; outputs in-place ----
    if (t0 < T_LEN) {
        const int base = t0 + (t0 >> 5);   // = tid*33, conflict-free stride
        if (rhalf) {
            #pragma unroll 8
            for (int j = 0; j < SEG; j++) {
                float xv = sh[base + j];
                if (j > 0)
                    M = OMS * M + S * xv;
                float L    = fast_log2(1e-6f + M);
                float sinv = fast_exp2(nalpha * L);
                float bse  = fmaf(xv, sinv, delta);      // > 0
                sh[base + j] = fast_sqrt(bse) - dr;
            }
        } else {
            #pragma unroll 8
            for (int j = 0; j < SEG; j++) {
                float xv = sh[base + j];
                if (j > 0)
                    M = OMS * M + S * xv;
                float L    = fast_log2(1e-6f + M);
                float sinv = fast_exp2(nalpha * L);
                float bse  = fmaf(xv, sinv, delta);
                sh[base + j] = fast_exp2(r * fast_log2(bse)) - dr;
            }
        }
    }

    __syncthreads();

    // ---- coalesced writeback (float4) ----
    float4* __restrict__ o4 = (float4*)outr;
    #pragma unroll
    for (int i = tid; i < T_LEN / 4; i += BLOCK) {
        int b = i * 4;
        float4 v;
        v.x = sh[SH_PAD(b + 0)];
        v.y = sh[SH_PAD(b + 1)];
        v.z = sh[SH_PAD(b + 2)];
        v.w = sh[SH_PAD(b + 3)];
        o4[i] = v;
    }
}

extern "C" void kernel_launch(void* const* d_in, const int* in_sizes, int n_in,
                              void* d_out, int out_size) {
    const float* mel   = (const float*)d_in[0];
    const float* alpha = (const float*)d_in[1];
    const float* delta = (const float*)d_in[2];
    const float* r     = (const float*)d_in[3];
    float* out = (float*)d_out;

    int rows = out_size / T_LEN;   // 128*128 = 16384
    pcen_kernel<<<rows, BLOCK>>>(mel, alpha, delta, r, out);
}

// round 5
// speedup vs baseline: 1.3557x; 1.0489x over previous
#include <cuda_runtime.h>
#include <cuda_bf16.h>
#include <cstdint>

#define T_LEN 4000
#define HALF  2000
#define BLOCK 128
#define SEG   16
#define NSEG  125          // segments per half
#define W     24           // truncated EMA taps: (1-s)^24 ~ 8e-6
// pad 4 floats per 32: 16B-aligned groups, conflict-free LDS.128
#define P16(i) ((i) + (((i) >> 5) << 2))

__device__ __forceinline__ float fast_exp2(float x) {
    float y; asm("ex2.approx.ftz.f32 %0, %1;" : "=f"(y) : "f"(x)); return y;
}
__device__ __forceinline__ float fast_log2(float x) {
    float y; asm("lg2.approx.ftz.f32 %0, %1;" : "=f"(y) : "f"(x)); return y;
}
__device__ __forceinline__ float fast_sqrt(float x) {
    float y; asm("sqrt.approx.ftz.f32 %0, %1;" : "=f"(y) : "f"(x)); return y;
}
__device__ __forceinline__ void cp_async16(uint32_t dst, const float* src) {
    asm volatile("cp.async.cg.shared.global [%0], [%1], 16;\n" :: "r"(dst), "l"(src));
}

struct Params { float delta, r, dr, nalpha; bool rhalf; };

__device__ __forceinline__ float pcen_elem(float xv, float M, const Params& p) {
    float L    = fast_log2(1e-6f + M);
    float sinv = fast_exp2(p.nalpha * L);
    float bse  = fmaf(xv, sinv, p.delta);            // > 0
    return (p.rhalf ? fast_sqrt(bse)
                    : fast_exp2(p.r * fast_log2(bse))) - p.dr;
}

__global__ __launch_bounds__(BLOCK) void pcen_kernel(
    const float* __restrict__ x,
    const float* __restrict__ alpha_p,
    const float* __restrict__ delta_p,
    const float* __restrict__ r_p,
    float* __restrict__ out)
{
    // data: P16(3999)+1 = 4496 floats; +24 floats tail-save
    __shared__ __align__(16) float sh[4496 + 24];
    float* shsave = sh + 4496;

    const int row = blockIdx.x;
    const int tid = threadIdx.x;
    const float* __restrict__ xr = x + (size_t)row * T_LEN;
    float* __restrict__ outr = out + (size_t)row * T_LEN;

    const uint32_t shaddr = (uint32_t)__cvta_generic_to_shared(sh);

    // ---- issue ALL loads async: group1 = half1 (chunks 0..499), group2 = half2 ----
    #pragma unroll
    for (int m = tid; m < 500; m += BLOCK)
        cp_async16(shaddr + 16u * m + 16u * (m >> 3), xr + 4 * m);
    asm volatile("cp.async.commit_group;\n" ::: "memory");
    #pragma unroll
    for (int m = 500 + tid; m < 1000; m += BLOCK)
        cp_async16(shaddr + 16u * m + 16u * (m >> 3), xr + 4 * m);
    asm volatile("cp.async.commit_group;\n" ::: "memory");

    // ---- scalar params (overlaps with async loads) ----
    Params p;
    float alpha = fminf(fmaxf(alpha_p[0], 0.01f), 0.99f);
    p.delta  = fabsf(delta_p[0]) + 1e-6f;
    p.r      = fminf(fmaxf(r_p[0], 0.01f), 1.0f);
    p.rhalf  = (p.r == 0.5f);
    p.dr     = p.rhalf ? fast_sqrt(p.delta)
                       : fast_exp2(p.r * fast_log2(p.delta));
    p.nalpha = -alpha;

    const float S    = 512.0f / 1323.0f;   // HOP/(SR*INIT_T) exact
    const float OMS  = 1.0f - S;
    const float INVS = 1323.0f / 512.0f;
    const bool  act  = tid < NSEG;

    // ================== PHASE 1 ==================
    asm volatile("cp.async.wait_group 1;\n" ::: "memory");
    __syncthreads();                           // BAR1: half1 staged

    // save half1 tail originals for phase-2 windows (segments 125/126)
    if (tid < 24) shsave[tid] = sh[P16(1976 + tid)];

    // window1: reconstruct M at t0 = 16*tid
    float M1 = 0.0f;
    if (act) {
        const int t0 = SEG * tid;
        if (tid == 0) {
            M1 = sh[P16(0)];                   // exact: M[0] = x[0]
        } else if (tid == 1) {
            // exact clamped expansion for t0 = 16 (< W)
            float acc = 0.0f, wj = S;
            #pragma unroll
            for (int j = 0; j < 16; j++) { acc += wj * sh[P16(16 - j)]; wj *= OMS; }
            acc += (wj * INVS) * sh[P16(0)];
            M1 = acc;
        } else {
            float acc = 0.0f, wj = S;
            #pragma unroll
            for (int j = 0; j < W; j++) { acc += wj * sh[P16(t0 - j)]; wj *= OMS; }
            M1 = acc;
        }
    }
    __syncthreads();                           // BAR2: window reads done

    // compute1 (in-place results in half1)
    if (act) {
        float M = M1;
        const int b = SEG * tid;
        #pragma unroll
        for (int q = 0; q < 4; q++) {
            float4 v = *(const float4*)&sh[P16(b + 4 * q)];
            float4 o;
            if (q > 0)        M = OMS * M + S * v.x;
            o.x = pcen_elem(v.x, M, p);
            M = OMS * M + S * v.y;  o.y = pcen_elem(v.y, M, p);
            M = OMS * M + S * v.z;  o.z = pcen_elem(v.z, M, p);
            M = OMS * M + S * v.w;  o.w = pcen_elem(v.w, M, p);
            *(float4*)&sh[P16(b + 4 * q)] = o;
        }
    }

    asm volatile("cp.async.wait_group 0;\n" ::: "memory");
    __syncthreads();                           // BAR3: results1 ready + half2 staged

    // writeback half1 (stores drain during phase 2)
    #pragma unroll
    for (int i = tid; i < 500; i += BLOCK) {
        float4 v = *(const float4*)&sh[P16(4 * i)];
        *(float4*)(outr + 4 * i) = v;
    }

    // ================== PHASE 2 ==================
    // window2: t0 = 2000 + 16*tid; segments 125/126 use saved tail
    float M2 = 0.0f;
    if (act) {
        const int t0 = HALF + SEG * tid;
        float acc = 0.0f, wj = S;
        if (tid >= 2) {
            #pragma unroll
            for (int j = 0; j < W; j++) { acc += wj * sh[P16(t0 - j)]; wj *= OMS; }
        } else {
            #pragma unroll
            for (int j = 0; j < W; j++) {
                int idx = t0 - j;
                float xv = (idx < HALF) ? shsave[idx - 1976] : sh[P16(idx)];
                acc += wj * xv; wj *= OMS;
            }
        }
        M2 = acc;
    }
    __syncthreads();                           // BAR4: window2 reads done

    // compute2 (in-place results in half2)
    if (act) {
        float M = M2;
        const int b = HALF + SEG * tid;
        #pragma unroll
        for (int q = 0; q < 4; q++) {
            float4 v = *(const float4*)&sh[P16(b + 4 * q)];
            float4 o;
            if (q > 0)        M = OMS * M + S * v.x;
            o.x = pcen_elem(v.x, M, p);
            M = OMS * M + S * v.y;  o.y = pcen_elem(v.y, M, p);
            M = OMS * M + S * v.z;  o.z = pcen_elem(v.z, M, p);
            M = OMS * M + S * v.w;  o.w = pcen_elem(v.w, M, p);
            *(float4*)&sh[P16(b + 4 * q)] = o;
        }
    }
    __syncthreads();                           // BAR5: results2 ready

    // writeback half2
    #pragma unroll
    for (int i = 500 + tid; i < 1000; i += BLOCK) {
        float4 v = *(const float4*)&sh[P16(4 * i)];
        *(float4*)(outr + 4 * i) = v;
    }
}

extern "C" void kernel_launch(void* const* d_in, const int* in_sizes, int n_in,
                              void* d_out, int out_size) {
    const float* mel   = (const float*)d_in[0];
    const float* alpha = (const float*)d_in[1];
    const float* delta = (const float*)d_in[2];
    const float* r     = (const float*)d_in[3];
    float* out = (float*)d_out;

    int rows = out_size / T_LEN;   // 128*128 = 16384
    pcen_kernel<<<rows, BLOCK>>>(mel, alpha, delta, r, out);
}